// round 13
// baseline (speedup 1.0000x reference)
#include <cuda_runtime.h>
#include <cstdint>

// ---------------------------------------------------------------------------
// GungnirHalfKA (NNUE) batched eval, GB300 sm_103a — Round 12
// 128-thread CTAs, 8 dims/thread: same instr total, ~2x warp parallelism.
// ---------------------------------------------------------------------------

#define FT_IN   45056
#define FT_OUT  1024
#define NB_MAX  8

__device__ signed char g_ftq[(size_t)FT_IN * FT_OUT];   // 46 MB, int8-exact
__device__ signed char g_fc0q[NB_MAX * 16 * FT_OUT];    // 128 KB, int8-exact
__device__ signed char g_fc1q[NB_MAX * 32 * 32];        // 8 KB, int8-exact
__device__ unsigned    g_bq[FT_OUT / 2];                // ft bias, 2x i16 packed
__device__ int         g_psq_part[16];                  // psqt nonzero partials

__device__ __forceinline__ float q8f(float x) {
    return fminf(fmaxf(rintf(x), -128.f), 127.f);
}
__device__ __forceinline__ float q16f(float x) {
    return fminf(fmaxf(rintf(x), -32768.f), 32767.f);
}
__device__ __forceinline__ float q32f(float x) {
    return fminf(fmaxf(rintf(x), -2147483648.f), 2147483647.f);
}
__device__ __forceinline__ float clip127(float x) {
    return fminf(fmaxf(x, 0.f), 127.f);
}

// Widen 4 packed int8 -> 2x(2x int16) and accumulate.
__device__ __forceinline__ void acc4(unsigned* a, unsigned v) {
    unsigned lo, hi;
    asm("prmt.b32 %0, %1, 0, 0x9180;" : "=r"(lo) : "r"(v));
    asm("prmt.b32 %0, %1, 0, 0xB3A2;" : "=r"(hi) : "r"(v));
    a[0] = __vadd2(a[0], lo);
    a[1] = __vadd2(a[1], hi);
}
__device__ __forceinline__ void acc8(unsigned* acc, const int2& v) {
    acc4(acc + 0, (unsigned)v.x);
    acc4(acc + 2, (unsigned)v.y);
}

// 4 byte-pair products (u8*u8 <= 16129, fits positive s16) -> 2 packed words.
__device__ __forceinline__ void mulbytes(unsigned a, unsigned c,
                                         int& lo, int& hi) {
    lo = (int)(((a & 0xFFu) * (c & 0xFFu)) |
               ((((a >> 8) & 0xFFu) * ((c >> 8) & 0xFFu)) << 16));
    hi = (int)((((a >> 16) & 0xFFu) * ((c >> 16) & 0xFFu)) |
               (((a >> 24) * (c >> 24)) << 16));
}

// signed byte j of word w -> float
__device__ __forceinline__ float sb2f(unsigned w, int j) {
    return (float)((int)(w << (24 - 8 * j)) >> 24);
}

__device__ __forceinline__ char4 q8x4(const float4& v) {
    char4 c;
    c.x = (signed char)q8f(v.x);
    c.y = (signed char)q8f(v.y);
    c.z = (signed char)q8f(v.z);
    c.w = (signed char)q8f(v.w);
    return c;
}

// ---- cvt grid layout (unchanged from R10) ---------------------------------
#define SCAN_BLOCKS 16
#define PSQ_F4      (FT_IN * 8 / 4)
#define PSQ_PER_BLK (PSQ_F4 / SCAN_BLOCKS)
#define FT_CVT      (FT_IN / 4)
#define FC0_F4      (NB_MAX * 16 * FT_OUT / 4)
#define FC0_CVT     (FC0_F4 / 1024)
#define FC1_F4      (NB_MAX * 32 * 32 / 4)
#define FC1_CVT     (FC1_F4 / 1024)
#define CVT_BLOCKS  (SCAN_BLOCKS + FT_CVT + FC0_CVT + FC1_CVT + 1)

__global__ void cvt_kernel(const float* __restrict__ ftw,
                           const float* __restrict__ f0w,
                           const float* __restrict__ f1w,
                           const float* __restrict__ ftb,
                           const float* __restrict__ psq) {
    const int blk = blockIdx.x;
    const int tid = threadIdx.x;

    if (blk < SCAN_BLOCKS) {
        int any = 0;
        const int base = blk * PSQ_PER_BLK;
        #pragma unroll 4
        for (int i = tid; i < PSQ_PER_BLK; i += 256) {
            float4 v = __ldcs(reinterpret_cast<const float4*>(psq) + base + i);
            any |= (v.x != 0.f) | (v.y != 0.f) | (v.z != 0.f) | (v.w != 0.f);
        }
        int r = __syncthreads_or(any);
        if (tid == 0) g_psq_part[blk] = r;
        return;
    }
    int k = blk - SCAN_BLOCKS;
    if (k < FT_CVT) {
        const size_t base = (size_t)k * 1024;
        #pragma unroll
        for (int j = 0; j < 4; j++) {
            size_t i = base + j * 256 + tid;
            float4 v = __ldcs(reinterpret_cast<const float4*>(ftw) + i);
            reinterpret_cast<char4*>(g_ftq)[i] = q8x4(v);
        }
        return;
    }
    k -= FT_CVT;
    if (k < FC0_CVT) {
        const int base = k * 1024;
        #pragma unroll
        for (int j = 0; j < 4; j++) {
            int i = base + j * 256 + tid;
            float4 v = __ldcs(reinterpret_cast<const float4*>(f0w) + i);
            reinterpret_cast<char4*>(g_fc0q)[i] = q8x4(v);
        }
        return;
    }
    k -= FC0_CVT;
    if (k < FC1_CVT) {
        const int base = k * 1024;
        #pragma unroll
        for (int j = 0; j < 4; j++) {
            int i = base + j * 256 + tid;
            float4 v = __ldcs(reinterpret_cast<const float4*>(f1w) + i);
            reinterpret_cast<char4*>(g_fc1q)[i] = q8x4(v);
        }
        return;
    }
    #pragma unroll
    for (int h = 0; h < 2; h++) {
        int w = tid * 2 + h;
        int b0 = (int)q16f(ftb[w * 2]);
        int b1 = (int)q16f(ftb[w * 2 + 1]);
        g_bq[w] = (unsigned)(b0 & 0xFFFF) | ((unsigned)b1 << 16);
    }
}

// ---- main fused kernel: one 128-thread CTA per batch item -----------------
__global__ __launch_bounds__(128, 14)
void nnue_kernel(const int* __restrict__ wf,  const int* __restrict__ wo,
                 const int* __restrict__ bf,  const int* __restrict__ bo,
                 const int* __restrict__ stm, const int* __restrict__ bucket,
                 const float* __restrict__ psq,
                 const float* __restrict__ fc0b,
                 const float* __restrict__ fc1b, const float* __restrict__ fc2w,
                 const float* __restrict__ fc2b,
                 float* __restrict__ out, int nfeat_total, int nb)
{
    const int b    = blockIdx.x;
    const int tid  = threadIdx.x;
    const int wid  = tid >> 5;
    const int lane = tid & 31;

    __shared__ __align__(16) int      s_wf[128], s_bf[128];
    __shared__ __align__(16) unsigned s_S[FT_OUT / 4];   // clipped acc_stm u8
    __shared__ __align__(16) unsigned s_O[FT_OUT / 4];   // clipped acc_opp u8
    __shared__ int   s_fc0p[64];                         // 4 warps x 16 partials
    __shared__ float s_o0[16];
    __shared__ float s_slab[32];
    __shared__ float s_psqt, s_scalar;
    __shared__ int   s_meta[4];

    if (tid == 0) {
        int ws = wo[b];
        int we = (b + 1 < nb) ? wo[b + 1] : nfeat_total;
        int bs = bo[b];
        int be = (b + 1 < nb) ? bo[b + 1] : nfeat_total;
        s_meta[0] = ws; s_meta[1] = min(we - ws, 128);
        s_meta[2] = bs; s_meta[3] = min(be - bs, 128);
    }
    __syncthreads();
    const int ws  = s_meta[0], nw  = s_meta[1];
    const int bs  = s_meta[2], nbf = s_meta[3];

    for (int i = tid; i < nw;  i += 128) s_wf[i] = wf[ws + i];
    for (int i = tid; i < nbf; i += 128) s_bf[i] = bf[bs + i];
    __syncthreads();

    const int st = stm[b];
    const int bk = bucket[b];
    const int d0 = tid * 8;                    // this thread's 8 dims

    // ---- gather both sides; clip+pack to u8, one STS.64 per side ---------
    #pragma unroll
    for (int side = 0; side < 2; side++) {
        const int* feats = side ? s_bf : s_wf;
        const int  n     = side ? nbf  : nw;
        unsigned acc[4] = {0,0,0,0};

        int f = 0;
        for (; f + 8 <= n; f += 8) {
            // 8 independent LDG.64 in flight (16 data regs).
            int4 ix0 = *reinterpret_cast<const int4*>(feats + f);
            int4 ix1 = *reinterpret_cast<const int4*>(feats + f + 4);
            int2 v0 = __ldcg(reinterpret_cast<const int2*>(g_ftq + ((size_t)ix0.x << 10) + d0));
            int2 v1 = __ldcg(reinterpret_cast<const int2*>(g_ftq + ((size_t)ix0.y << 10) + d0));
            int2 v2 = __ldcg(reinterpret_cast<const int2*>(g_ftq + ((size_t)ix0.z << 10) + d0));
            int2 v3 = __ldcg(reinterpret_cast<const int2*>(g_ftq + ((size_t)ix0.w << 10) + d0));
            int2 v4 = __ldcg(reinterpret_cast<const int2*>(g_ftq + ((size_t)ix1.x << 10) + d0));
            int2 v5 = __ldcg(reinterpret_cast<const int2*>(g_ftq + ((size_t)ix1.y << 10) + d0));
            int2 v6 = __ldcg(reinterpret_cast<const int2*>(g_ftq + ((size_t)ix1.z << 10) + d0));
            int2 v7 = __ldcg(reinterpret_cast<const int2*>(g_ftq + ((size_t)ix1.w << 10) + d0));
            acc8(acc, v0); acc8(acc, v1); acc8(acc, v2); acc8(acc, v3);
            acc8(acc, v4); acc8(acc, v5); acc8(acc, v6); acc8(acc, v7);
        }
        for (; f < n; f++) {
            const int2 v = __ldcg(reinterpret_cast<const int2*>(
                g_ftq + ((size_t)feats[f] << 10) + d0));
            acc8(acc, v);
        }

        // Bias: one uint4 load (words 4*tid .. 4*tid+3 cover dims d0..d0+7).
        const uint4 bq = reinterpret_cast<const uint4*>(g_bq)[tid];
        const unsigned biasp[4] = {bq.x, bq.y, bq.z, bq.w};

        unsigned pw[2];
        #pragma unroll
        for (int j = 0; j < 2; j++) {
            unsigned a01 = __vadd2(acc[2*j],     biasp[2*j]);
            unsigned a23 = __vadd2(acc[2*j + 1], biasp[2*j + 1]);
            a01 = __vmins2(__vmaxs2(a01, 0u), 0x007F007Fu);
            a23 = __vmins2(__vmaxs2(a23, 0u), 0x007F007Fu);
            pw[j] = __byte_perm(a01, a23, 0x6420);
        }
        unsigned* dst = (side ^ st) ? s_O : s_S;
        *reinterpret_cast<uint2*>(dst + 2 * tid) = make_uint2(pw[0], pw[1]);
    }
    __syncthreads();

    // ---- pairwise products for MY 8 product dims, kept in registers ------
    // Thread t owns product dims [8t, 8t+8): t<64 from S-half, t>=64 from O.
    int prod[4];
    {
        const unsigned* src = (tid < 64) ? s_S : s_O;
        const int tt = tid & 63;
        uint2 A = *reinterpret_cast<const uint2*>(src + 2 * tt);
        uint2 C = *reinterpret_cast<const uint2*>(src + 2 * tt + 128);
        mulbytes(A.x, C.x, prod[0], prod[1]);
        mulbytes(A.y, C.y, prod[2], prod[3]);
    }

    // ---- fc0: all threads, all 16 outputs over own dims; REDUX per warp --
    {
        const signed char* wbase = g_fc0q + (bk << 14) + 8 * tid;
        #pragma unroll
        for (int o = 0; o < 16; o++) {
            int2 wv = *reinterpret_cast<const int2*>(wbase + (o << 10));
            int s = 0;
            s = __dp2a_lo(prod[0], wv.x, s);
            s = __dp2a_hi(prod[1], wv.x, s);
            s = __dp2a_lo(prod[2], wv.y, s);
            s = __dp2a_hi(prod[3], wv.y, s);
            int rsum = (int)__reduce_add_sync(0xffffffffu, (unsigned)s);
            if (lane == o) s_fc0p[wid * 16 + o] = rsum;
        }
    }
    __syncthreads();

    // ---- warp 1: psqt (only if table nonzero); warp 0: tail MLP ----------
    if (wid == 1) {
        int nzp = (lane < 16) ? g_psq_part[lane] : 0;
        if (__any_sync(0xffffffffu, nzp)) {
            float ps = 0.f;
            for (int i = lane; i < nw;  i += 32)
                ps += q32f(psq[(size_t)s_wf[i] * 8 + bk]);
            for (int i = lane; i < nbf; i += 32)
                ps -= q32f(psq[(size_t)s_bf[i] * 8 + bk]);
            #pragma unroll
            for (int off = 16; off; off >>= 1)
                ps += __shfl_down_sync(0xffffffffu, ps, off);
            if (lane == 0) s_psqt = (st ? -ps : ps) * 0.5f;
        } else if (lane == 0) {
            s_psqt = 0.f;
        }
    } else if (wid == 0) {
        // o0: combine 4 warp partials
        if (lane < 16) {
            int isum = s_fc0p[lane] + s_fc0p[16 + lane]
                     + s_fc0p[32 + lane] + s_fc0p[48 + lane];
            s_o0[lane] = (float)isum * (1.f / 128.f) + q32f(fc0b[bk * 16 + lane]);
        }
        __syncwarp();

        float sl = 0.f;
        if (lane < 15) {
            float v = s_o0[lane];
            sl = clip127(v * v * (1.f / 524288.f));       // 1<<19
        } else if (lane < 30) {
            float v = s_o0[lane - 15];
            sl = clip127(v * (1.f / 64.f));
        }
        s_slab[lane] = sl;
        __syncwarp();

        // fc1: int8 weights, lane's row = 32 B -> 2x LDG.128
        const signed char* w1 = g_fc1q + (bk * 32 + lane) * 32;
        uint4 wa = *reinterpret_cast<const uint4*>(w1);
        uint4 wb = *reinterpret_cast<const uint4*>(w1 + 16);
        const unsigned ww[8] = {wa.x, wa.y, wa.z, wa.w, wb.x, wb.y, wb.z, wb.w};
        float o1 = 0.f;
        #pragma unroll
        for (int q = 0; q < 8; q++) {
            o1 += s_slab[4*q + 0] * sb2f(ww[q], 0);
            o1 += s_slab[4*q + 1] * sb2f(ww[q], 1);
            o1 += s_slab[4*q + 2] * sb2f(ww[q], 2);
            o1 += s_slab[4*q + 3] * sb2f(ww[q], 3);
        }
        o1 += q32f(fc1b[bk * 32 + lane]);

        float a1 = clip127(o1 * (1.f / 64.f));
        float p  = a1 * q8f(fc2w[bk * 32 + lane]);
        #pragma unroll
        for (int off = 16; off; off >>= 1)
            p += __shfl_down_sync(0xffffffffu, p, off);
        if (lane == 0) {
            float scalar = p + q32f(fc2b[bk]);
            float skip   = s_o0[15] * (9600.f / 8128.f);
            s_scalar = scalar + skip;
        }
    }
    __syncthreads();

    if (tid == 0)
        out[b] = (s_psqt + s_scalar) * (1.f / 16.f);
}

extern "C" void kernel_launch(void* const* d_in, const int* in_sizes, int n_in,
                              void* d_out, int out_size)
{
    const int*   wf   = (const int*)d_in[0];
    const int*   wo   = (const int*)d_in[1];
    const int*   bfi  = (const int*)d_in[2];
    const int*   bo   = (const int*)d_in[3];
    const int*   stm  = (const int*)d_in[4];
    const int*   bkt  = (const int*)d_in[5];
    const float* ftw  = (const float*)d_in[6];
    const float* ftb  = (const float*)d_in[7];
    const float* psq  = (const float*)d_in[8];
    const float* f0w  = (const float*)d_in[9];
    const float* f0b  = (const float*)d_in[10];
    const float* f1w  = (const float*)d_in[11];
    const float* f1b  = (const float*)d_in[12];
    const float* f2w  = (const float*)d_in[13];
    const float* f2b  = (const float*)d_in[14];
    float* out = (float*)d_out;

    const int nb = in_sizes[4];
    const int nfeat_total = in_sizes[0];

    cvt_kernel<<<CVT_BLOCKS, 256>>>(ftw, f0w, f1w, ftb, psq);

    nnue_kernel<<<nb, 128>>>(wf, wo, bfi, bo, stm, bkt,
                             psq, f0b, f1b, f2w, f2b,
                             out, nfeat_total, nb);
}